// round 1
// baseline (speedup 1.0000x reference)
#include <cuda_runtime.h>
#include <cuda_bf16.h>
#include <math.h>

#define S_LEN 2048
#define DIM 4096
#define N_HEADS 32
#define N_KV_HEADS 8
#define HEAD_DIM 128
#define KV_DIM (N_KV_HEADS * HEAD_DIM)   // 1024

// Scratch (allocation-free rule: __device__ globals)
__device__ float g_q[S_LEN * DIM];       // 32 MB
__device__ float g_k[S_LEN * KV_DIM];    // 8 MB
__device__ float g_v[S_LEN * KV_DIM];    // 8 MB
__device__ float g_ao[S_LEN * DIM];      // 32 MB

// ---------------------------------------------------------------------------
// Tiled FP32 GEMM: C[M,N] = A[M,K] @ B[K,N], all row-major, dims divisible.
// BM=BN=128, BK=8, TM=TN=8, 256 threads.
// ---------------------------------------------------------------------------
__global__ __launch_bounds__(256) void sgemm_kernel(
    const float* __restrict__ A, const float* __restrict__ B,
    float* __restrict__ C, int M, int N, int K)
{
    const int BM = 128, BN = 128, BK = 8;
    __shared__ float As[BK][BM];        // transposed A tile
    __shared__ float Bs[BK][BN];

    int tid = threadIdx.x;
    int tx = tid & 15;        // 0..15 (N dir)
    int ty = tid >> 4;        // 0..15 (M dir)

    const float* Ab = A + (size_t)blockIdx.y * BM * K;
    const float* Bb = B + (size_t)blockIdx.x * BN;

    float acc[8][8];
    #pragma unroll
    for (int i = 0; i < 8; i++)
        #pragma unroll
        for (int j = 0; j < 8; j++) acc[i][j] = 0.0f;

    // A tile load map: 128 rows x 8 cols = 256 float4
    int arow = tid >> 1;
    int acol = (tid & 1) * 4;
    // B tile load map: 8 rows x 128 cols = 256 float4
    int brow = tid >> 5;
    int bcol = (tid & 31) * 4;

    for (int k0 = 0; k0 < K; k0 += BK) {
        float4 a4 = *(const float4*)(Ab + (size_t)arow * K + k0 + acol);
        As[acol + 0][arow] = a4.x;
        As[acol + 1][arow] = a4.y;
        As[acol + 2][arow] = a4.z;
        As[acol + 3][arow] = a4.w;
        *(float4*)&Bs[brow][bcol] =
            *(const float4*)(Bb + (size_t)(k0 + brow) * N + bcol);
        __syncthreads();

        #pragma unroll
        for (int kk = 0; kk < BK; kk++) {
            float4 a0 = *(float4*)&As[kk][ty * 8];
            float4 a1 = *(float4*)&As[kk][ty * 8 + 4];
            float4 b0 = *(float4*)&Bs[kk][tx * 8];
            float4 b1 = *(float4*)&Bs[kk][tx * 8 + 4];
            float ar[8] = {a0.x, a0.y, a0.z, a0.w, a1.x, a1.y, a1.z, a1.w};
            float br[8] = {b0.x, b0.y, b0.z, b0.w, b1.x, b1.y, b1.z, b1.w};
            #pragma unroll
            for (int i = 0; i < 8; i++)
                #pragma unroll
                for (int j = 0; j < 8; j++)
                    acc[i][j] = fmaf(ar[i], br[j], acc[i][j]);
        }
        __syncthreads();
    }

    float* Cb = C + (size_t)(blockIdx.y * BM) * N + blockIdx.x * BN;
    #pragma unroll
    for (int i = 0; i < 8; i++) {
        int r = ty * 8 + i;
        float4 v0 = {acc[i][0], acc[i][1], acc[i][2], acc[i][3]};
        float4 v1 = {acc[i][4], acc[i][5], acc[i][6], acc[i][7]};
        *(float4*)(Cb + (size_t)r * N + tx * 8)     = v0;
        *(float4*)(Cb + (size_t)r * N + tx * 8 + 4) = v1;
    }
}

// ---------------------------------------------------------------------------
// RoPE (interleaved pairs): t0' = t0*c - t1*s ; t1' = t0*s + t1*c
// T: (S_LEN, nheads*128). One thread per (s, head, pair).
// ---------------------------------------------------------------------------
__global__ void rope_kernel(float* __restrict__ T,
                            const float* __restrict__ cosb,
                            const float* __restrict__ sinb,
                            int nheads)
{
    int idx = blockIdx.x * blockDim.x + threadIdx.x;
    int total = S_LEN * nheads * (HEAD_DIM / 2);
    if (idx >= total) return;
    int d2 = idx & 63;
    int t  = idx >> 6;
    int h  = t % nheads;
    int s  = t / nheads;
    float c  = cosb[s * 64 + d2];
    float sn = sinb[s * 64 + d2];
    float2* p = (float2*)(T + (size_t)s * nheads * HEAD_DIM + h * HEAD_DIM + d2 * 2);
    float2 v = *p;
    float2 o;
    o.x = v.x * c - v.y * sn;
    o.y = v.x * sn + v.y * c;
    *p = o;
}

// ---------------------------------------------------------------------------
// Flash-attention (fp32, non-causal, full softmax, GQA 4:1)
// grid = (S/BR, N_HEADS), 256 threads. Br=Bc=64, D=128.
// Thread (ty,tx): owns S rows ty*4+i, S cols tx+16*j; O cols tx*8..tx*8+7.
// ---------------------------------------------------------------------------
#define BR 64
#define BC 64
#define DPAD 132
#define PCPAD 68

__global__ __launch_bounds__(256) void attn_kernel(
    const float* __restrict__ Q, const float* __restrict__ K,
    const float* __restrict__ V, float* __restrict__ O)
{
    extern __shared__ float sm[];
    float* Qs = sm;                       // BR * DPAD
    float* Ks = Qs + BR * DPAD;           // BC * DPAD
    float* Vs = Ks + BC * DPAD;           // BC * DPAD
    float* Ps = Vs + BC * DPAD;           // BR * PCPAD

    const int h   = blockIdx.y;
    const int kvh = h >> 2;               // 32 heads -> 8 kv heads
    const int q0  = blockIdx.x * BR;
    const int tid = threadIdx.x;
    const int tx  = tid & 15;
    const int ty  = tid >> 4;
    const float scale = 0.08838834764831845f;   // 1/sqrt(128)

    // Load Q tile (scaled)
    for (int idx = tid; idx < BR * 32; idx += 256) {
        int r = idx >> 5, d4 = (idx & 31) * 4;
        float4 v = *(const float4*)(Q + (size_t)(q0 + r) * DIM + h * HEAD_DIM + d4);
        v.x *= scale; v.y *= scale; v.z *= scale; v.w *= scale;
        *(float4*)&Qs[r * DPAD + d4] = v;
    }

    float m_i[4], l_i[4], acc[4][8];
    #pragma unroll
    for (int i = 0; i < 4; i++) {
        m_i[i] = -1e30f; l_i[i] = 0.0f;
        #pragma unroll
        for (int c = 0; c < 8; c++) acc[i][c] = 0.0f;
    }
    __syncthreads();

    for (int kb = 0; kb < S_LEN; kb += BC) {
        // Load K,V tiles
        for (int idx = tid; idx < BC * 32; idx += 256) {
            int r = idx >> 5, d4 = (idx & 31) * 4;
            *(float4*)&Ks[r * DPAD + d4] =
                *(const float4*)(K + (size_t)(kb + r) * KV_DIM + kvh * HEAD_DIM + d4);
            *(float4*)&Vs[r * DPAD + d4] =
                *(const float4*)(V + (size_t)(kb + r) * KV_DIM + kvh * HEAD_DIM + d4);
        }
        __syncthreads();

        // S = Qs @ Ks^T  (4 rows x 4 strided cols per thread)
        float s[4][4];
        #pragma unroll
        for (int i = 0; i < 4; i++)
            #pragma unroll
            for (int j = 0; j < 4; j++) s[i][j] = 0.0f;

        for (int d = 0; d < HEAD_DIM; d += 4) {
            float4 q[4], k[4];
            #pragma unroll
            for (int i = 0; i < 4; i++)
                q[i] = *(float4*)&Qs[(ty * 4 + i) * DPAD + d];
            #pragma unroll
            for (int j = 0; j < 4; j++)
                k[j] = *(float4*)&Ks[(tx + 16 * j) * DPAD + d];
            #pragma unroll
            for (int i = 0; i < 4; i++)
                #pragma unroll
                for (int j = 0; j < 4; j++) {
                    s[i][j] = fmaf(q[i].x, k[j].x, s[i][j]);
                    s[i][j] = fmaf(q[i].y, k[j].y, s[i][j]);
                    s[i][j] = fmaf(q[i].z, k[j].z, s[i][j]);
                    s[i][j] = fmaf(q[i].w, k[j].w, s[i][j]);
                }
        }

        // Online softmax
        float mt[4], lt[4], alpha[4];
        #pragma unroll
        for (int i = 0; i < 4; i++) {
            mt[i] = fmaxf(fmaxf(s[i][0], s[i][1]), fmaxf(s[i][2], s[i][3]));
            #pragma unroll
            for (int off = 8; off >= 1; off >>= 1)
                mt[i] = fmaxf(mt[i], __shfl_xor_sync(0xffffffffu, mt[i], off, 16));
            float mn = fmaxf(m_i[i], mt[i]);
            alpha[i] = __expf(m_i[i] - mn);
            m_i[i] = mn;
            lt[i] = 0.0f;
            #pragma unroll
            for (int j = 0; j < 4; j++) {
                float p = __expf(s[i][j] - mn);
                s[i][j] = p;
                lt[i] += p;
            }
            #pragma unroll
            for (int off = 8; off >= 1; off >>= 1)
                lt[i] += __shfl_xor_sync(0xffffffffu, lt[i], off, 16);
            l_i[i] = l_i[i] * alpha[i] + lt[i];
            #pragma unroll
            for (int c = 0; c < 8; c++) acc[i][c] *= alpha[i];
            // store P (col = tx + 16j)
            #pragma unroll
            for (int j = 0; j < 4; j++)
                Ps[(ty * 4 + i) * PCPAD + tx + 16 * j] = s[i][j];
        }
        __syncthreads();

        // O += P @ V  (thread cols tx*8 .. tx*8+7)
        for (int j = 0; j < BC; j++) {
            float p0 = Ps[(ty * 4 + 0) * PCPAD + j];
            float p1 = Ps[(ty * 4 + 1) * PCPAD + j];
            float p2 = Ps[(ty * 4 + 2) * PCPAD + j];
            float p3 = Ps[(ty * 4 + 3) * PCPAD + j];
            float4 va = *(float4*)&Vs[j * DPAD + tx * 8];
            float4 vb = *(float4*)&Vs[j * DPAD + tx * 8 + 4];
            float vv[8] = {va.x, va.y, va.z, va.w, vb.x, vb.y, vb.z, vb.w};
            float pp[4] = {p0, p1, p2, p3};
            #pragma unroll
            for (int i = 0; i < 4; i++)
                #pragma unroll
                for (int c = 0; c < 8; c++)
                    acc[i][c] = fmaf(pp[i], vv[c], acc[i][c]);
        }
        __syncthreads();
    }

    // Normalize + write O
    #pragma unroll
    for (int i = 0; i < 4; i++) {
        float inv = 1.0f / l_i[i];
        int r = q0 + ty * 4 + i;
        float4 v0 = {acc[i][0] * inv, acc[i][1] * inv, acc[i][2] * inv, acc[i][3] * inv};
        float4 v1 = {acc[i][4] * inv, acc[i][5] * inv, acc[i][6] * inv, acc[i][7] * inv};
        *(float4*)(O + (size_t)r * DIM + h * HEAD_DIM + tx * 8)     = v0;
        *(float4*)(O + (size_t)r * DIM + h * HEAD_DIM + tx * 8 + 4) = v1;
    }
}

// ---------------------------------------------------------------------------
extern "C" void kernel_launch(void* const* d_in, const int* in_sizes, int n_in,
                              void* d_out, int out_size)
{
    const float* x  = (const float*)d_in[0];
    const float* fc = (const float*)d_in[1];
    const float* fs = (const float*)d_in[2];
    const float* wq = (const float*)d_in[3];
    const float* wk = (const float*)d_in[4];
    const float* wv = (const float*)d_in[5];
    const float* wo = (const float*)d_in[6];
    float* out = (float*)d_out;

    float *q, *k, *v, *ao;
    cudaGetSymbolAddress((void**)&q,  g_q);
    cudaGetSymbolAddress((void**)&k,  g_k);
    cudaGetSymbolAddress((void**)&v,  g_v);
    cudaGetSymbolAddress((void**)&ao, g_ao);

    // QKV projections
    sgemm_kernel<<<dim3(DIM / 128, S_LEN / 128), 256>>>(x, wq, q, S_LEN, DIM, DIM);
    sgemm_kernel<<<dim3(KV_DIM / 128, S_LEN / 128), 256>>>(x, wk, k, S_LEN, KV_DIM, DIM);
    sgemm_kernel<<<dim3(KV_DIM / 128, S_LEN / 128), 256>>>(x, wv, v, S_LEN, KV_DIM, DIM);

    // RoPE on Q and K
    rope_kernel<<<(S_LEN * N_HEADS * 64) / 256, 256>>>(q, fc, fs, N_HEADS);
    rope_kernel<<<(S_LEN * N_KV_HEADS * 64) / 256, 256>>>(k, fc, fs, N_KV_HEADS);

    // Attention
    int smem = (BR * DPAD + 2 * BC * DPAD + BR * PCPAD) * (int)sizeof(float);
    cudaFuncSetAttribute(attn_kernel, cudaFuncAttributeMaxDynamicSharedMemorySize, smem);
    attn_kernel<<<dim3(S_LEN / BR, N_HEADS), 256, smem>>>(q, k, v, ao);

    // Output projection
    sgemm_kernel<<<dim3(DIM / 128, S_LEN / 128), 256>>>(ao, wo, out, S_LEN, DIM, DIM);
}

// round 2
// speedup vs baseline: 1.5926x; 1.5926x over previous
#include <cuda_runtime.h>
#include <cuda_bf16.h>
#include <math.h>

#define S_LEN 2048
#define DIM 4096
#define N_HEADS 32
#define N_KV_HEADS 8
#define HEAD_DIM 128
#define KV_DIM (N_KV_HEADS * HEAD_DIM)   // 1024

// Scratch (allocation-free rule: __device__ globals)
__device__ float g_q[S_LEN * DIM];       // 32 MB
__device__ float g_k[S_LEN * KV_DIM];    // 8 MB
__device__ float g_v[S_LEN * KV_DIM];    // 8 MB
__device__ float g_ao[S_LEN * DIM];      // 32 MB

// ---------------------------------------------------------------------------
// Tiled FP32 GEMM: C[M,N] = A[M,K] @ B[K,N], all row-major, dims divisible.
// BM=BN=128, BK=8, TM=TN=8, 256 threads.
// ---------------------------------------------------------------------------
__global__ __launch_bounds__(256) void sgemm_kernel(
    const float* __restrict__ A, const float* __restrict__ B,
    float* __restrict__ C, int M, int N, int K)
{
    const int BM = 128, BN = 128, BK = 8;
    __shared__ float As[BK][BM];        // transposed A tile
    __shared__ float Bs[BK][BN];

    int tid = threadIdx.x;
    int tx = tid & 15;        // 0..15 (N dir)
    int ty = tid >> 4;        // 0..15 (M dir)

    const float* Ab = A + (size_t)blockIdx.y * BM * K;
    const float* Bb = B + (size_t)blockIdx.x * BN;

    float acc[8][8];
    #pragma unroll
    for (int i = 0; i < 8; i++)
        #pragma unroll
        for (int j = 0; j < 8; j++) acc[i][j] = 0.0f;

    // A tile load map: 128 rows x 8 cols = 256 float4
    int arow = tid >> 1;
    int acol = (tid & 1) * 4;
    // B tile load map: 8 rows x 128 cols = 256 float4
    int brow = tid >> 5;
    int bcol = (tid & 31) * 4;

    for (int k0 = 0; k0 < K; k0 += BK) {
        float4 a4 = *(const float4*)(Ab + (size_t)arow * K + k0 + acol);
        As[acol + 0][arow] = a4.x;
        As[acol + 1][arow] = a4.y;
        As[acol + 2][arow] = a4.z;
        As[acol + 3][arow] = a4.w;
        *(float4*)&Bs[brow][bcol] =
            *(const float4*)(Bb + (size_t)(k0 + brow) * N + bcol);
        __syncthreads();

        #pragma unroll
        for (int kk = 0; kk < BK; kk++) {
            float4 a0 = *(float4*)&As[kk][ty * 8];
            float4 a1 = *(float4*)&As[kk][ty * 8 + 4];
            float4 b0 = *(float4*)&Bs[kk][tx * 8];
            float4 b1 = *(float4*)&Bs[kk][tx * 8 + 4];
            float ar[8] = {a0.x, a0.y, a0.z, a0.w, a1.x, a1.y, a1.z, a1.w};
            float br[8] = {b0.x, b0.y, b0.z, b0.w, b1.x, b1.y, b1.z, b1.w};
            #pragma unroll
            for (int i = 0; i < 8; i++)
                #pragma unroll
                for (int j = 0; j < 8; j++)
                    acc[i][j] = fmaf(ar[i], br[j], acc[i][j]);
        }
        __syncthreads();
    }

    float* Cb = C + (size_t)(blockIdx.y * BM) * N + blockIdx.x * BN;
    #pragma unroll
    for (int i = 0; i < 8; i++) {
        int r = ty * 8 + i;
        float4 v0 = {acc[i][0], acc[i][1], acc[i][2], acc[i][3]};
        float4 v1 = {acc[i][4], acc[i][5], acc[i][6], acc[i][7]};
        *(float4*)(Cb + (size_t)r * N + tx * 8)     = v0;
        *(float4*)(Cb + (size_t)r * N + tx * 8 + 4) = v1;
    }
}

// ---------------------------------------------------------------------------
// RoPE (interleaved pairs): t0' = t0*c - t1*s ; t1' = t0*s + t1*c
// T: (S_LEN, nheads*128). One thread per (s, head, pair).
// ---------------------------------------------------------------------------
__global__ void rope_kernel(float* __restrict__ T,
                            const float* __restrict__ cosb,
                            const float* __restrict__ sinb,
                            int nheads)
{
    int idx = blockIdx.x * blockDim.x + threadIdx.x;
    int total = S_LEN * nheads * (HEAD_DIM / 2);
    if (idx >= total) return;
    int d2 = idx & 63;
    int t  = idx >> 6;
    int h  = t % nheads;
    int s  = t / nheads;
    float c  = cosb[s * 64 + d2];
    float sn = sinb[s * 64 + d2];
    float2* p = (float2*)(T + (size_t)s * nheads * HEAD_DIM + h * HEAD_DIM + d2 * 2);
    float2 v = *p;
    float2 o;
    o.x = v.x * c - v.y * sn;
    o.y = v.x * sn + v.y * c;
    *p = o;
}

// ---------------------------------------------------------------------------
// Flash-attention (fp32, non-causal, full softmax, GQA 4:1)
// grid = (S/BR, N_HEADS), 256 threads. Br=Bc=64, D=128.
// Thread (ty,tx): owns S rows ty*4+i, S cols tx+16*j; O cols tx*8..tx*8+7.
// ---------------------------------------------------------------------------
#define BR 64
#define BC 64
#define DPAD 132
#define PCPAD 68

__global__ __launch_bounds__(256) void attn_kernel(
    const float* __restrict__ Q, const float* __restrict__ K,
    const float* __restrict__ V, float* __restrict__ O)
{
    extern __shared__ float sm[];
    float* Qs = sm;                       // BR * DPAD
    float* Ks = Qs + BR * DPAD;           // BC * DPAD
    float* Vs = Ks + BC * DPAD;           // BC * DPAD
    float* Ps = Vs + BC * DPAD;           // BR * PCPAD

    const int h   = blockIdx.y;
    const int kvh = h >> 2;               // 32 heads -> 8 kv heads
    const int q0  = blockIdx.x * BR;
    const int tid = threadIdx.x;
    const int tx  = tid & 15;
    const int ty  = tid >> 4;
    const float scale = 0.08838834764831845f;   // 1/sqrt(128)

    // Load Q tile (scaled)
    for (int idx = tid; idx < BR * 32; idx += 256) {
        int r = idx >> 5, d4 = (idx & 31) * 4;
        float4 v = *(const float4*)(Q + (size_t)(q0 + r) * DIM + h * HEAD_DIM + d4);
        v.x *= scale; v.y *= scale; v.z *= scale; v.w *= scale;
        *(float4*)&Qs[r * DPAD + d4] = v;
    }

    float m_i[4], l_i[4], acc[4][8];
    #pragma unroll
    for (int i = 0; i < 4; i++) {
        m_i[i] = -1e30f; l_i[i] = 0.0f;
        #pragma unroll
        for (int c = 0; c < 8; c++) acc[i][c] = 0.0f;
    }
    __syncthreads();

    for (int kb = 0; kb < S_LEN; kb += BC) {
        // Load K,V tiles
        for (int idx = tid; idx < BC * 32; idx += 256) {
            int r = idx >> 5, d4 = (idx & 31) * 4;
            *(float4*)&Ks[r * DPAD + d4] =
                *(const float4*)(K + (size_t)(kb + r) * KV_DIM + kvh * HEAD_DIM + d4);
            *(float4*)&Vs[r * DPAD + d4] =
                *(const float4*)(V + (size_t)(kb + r) * KV_DIM + kvh * HEAD_DIM + d4);
        }
        __syncthreads();

        // S = Qs @ Ks^T  (4 rows x 4 strided cols per thread)
        float s[4][4];
        #pragma unroll
        for (int i = 0; i < 4; i++)
            #pragma unroll
            for (int j = 0; j < 4; j++) s[i][j] = 0.0f;

        for (int d = 0; d < HEAD_DIM; d += 4) {
            float4 q[4], k[4];
            #pragma unroll
            for (int i = 0; i < 4; i++)
                q[i] = *(float4*)&Qs[(ty * 4 + i) * DPAD + d];
            #pragma unroll
            for (int j = 0; j < 4; j++)
                k[j] = *(float4*)&Ks[(tx + 16 * j) * DPAD + d];
            #pragma unroll
            for (int i = 0; i < 4; i++)
                #pragma unroll
                for (int j = 0; j < 4; j++) {
                    s[i][j] = fmaf(q[i].x, k[j].x, s[i][j]);
                    s[i][j] = fmaf(q[i].y, k[j].y, s[i][j]);
                    s[i][j] = fmaf(q[i].z, k[j].z, s[i][j]);
                    s[i][j] = fmaf(q[i].w, k[j].w, s[i][j]);
                }
        }

        // Online softmax
        float mt[4], lt[4], alpha[4];
        #pragma unroll
        for (int i = 0; i < 4; i++) {
            mt[i] = fmaxf(fmaxf(s[i][0], s[i][1]), fmaxf(s[i][2], s[i][3]));
            #pragma unroll
            for (int off = 8; off >= 1; off >>= 1)
                mt[i] = fmaxf(mt[i], __shfl_xor_sync(0xffffffffu, mt[i], off, 16));
            float mn = fmaxf(m_i[i], mt[i]);
            alpha[i] = __expf(m_i[i] - mn);
            m_i[i] = mn;
            lt[i] = 0.0f;
            #pragma unroll
            for (int j = 0; j < 4; j++) {
                float p = __expf(s[i][j] - mn);
                s[i][j] = p;
                lt[i] += p;
            }
            #pragma unroll
            for (int off = 8; off >= 1; off >>= 1)
                lt[i] += __shfl_xor_sync(0xffffffffu, lt[i], off, 16);
            l_i[i] = l_i[i] * alpha[i] + lt[i];
            #pragma unroll
            for (int c = 0; c < 8; c++) acc[i][c] *= alpha[i];
            // store P (col = tx + 16j)
            #pragma unroll
            for (int j = 0; j < 4; j++)
                Ps[(ty * 4 + i) * PCPAD + tx + 16 * j] = s[i][j];
        }
        __syncthreads();

        // O += P @ V  (thread cols tx*8 .. tx*8+7)
        for (int j = 0; j < BC; j++) {
            float p0 = Ps[(ty * 4 + 0) * PCPAD + j];
            float p1 = Ps[(ty * 4 + 1) * PCPAD + j];
            float p2 = Ps[(ty * 4 + 2) * PCPAD + j];
            float p3 = Ps[(ty * 4 + 3) * PCPAD + j];
            float4 va = *(float4*)&Vs[j * DPAD + tx * 8];
            float4 vb = *(float4*)&Vs[j * DPAD + tx * 8 + 4];
            float vv[8] = {va.x, va.y, va.z, va.w, vb.x, vb.y, vb.z, vb.w};
            float pp[4] = {p0, p1, p2, p3};
            #pragma unroll
            for (int i = 0; i < 4; i++)
                #pragma unroll
                for (int c = 0; c < 8; c++)
                    acc[i][c] = fmaf(pp[i], vv[c], acc[i][c]);
        }
        __syncthreads();
    }

    // Normalize + write O
    #pragma unroll
    for (int i = 0; i < 4; i++) {
        float inv = 1.0f / l_i[i];
        int r = q0 + ty * 4 + i;
        float4 v0 = {acc[i][0] * inv, acc[i][1] * inv, acc[i][2] * inv, acc[i][3] * inv};
        float4 v1 = {acc[i][4] * inv, acc[i][5] * inv, acc[i][6] * inv, acc[i][7] * inv};
        *(float4*)(O + (size_t)r * DIM + h * HEAD_DIM + tx * 8)     = v0;
        *(float4*)(O + (size_t)r * DIM + h * HEAD_DIM + tx * 8 + 4) = v1;
    }
}

// ---------------------------------------------------------------------------
extern "C" void kernel_launch(void* const* d_in, const int* in_sizes, int n_in,
                              void* d_out, int out_size)
{
    const float* x  = (const float*)d_in[0];
    const float* fc = (const float*)d_in[1];
    const float* fs = (const float*)d_in[2];
    const float* wq = (const float*)d_in[3];
    const float* wk = (const float*)d_in[4];
    const float* wv = (const float*)d_in[5];
    const float* wo = (const float*)d_in[6];
    float* out = (float*)d_out;

    float *q, *k, *v, *ao;
    cudaGetSymbolAddress((void**)&q,  g_q);
    cudaGetSymbolAddress((void**)&k,  g_k);
    cudaGetSymbolAddress((void**)&v,  g_v);
    cudaGetSymbolAddress((void**)&ao, g_ao);

    // QKV projections
    sgemm_kernel<<<dim3(DIM / 128, S_LEN / 128), 256>>>(x, wq, q, S_LEN, DIM, DIM);
    sgemm_kernel<<<dim3(KV_DIM / 128, S_LEN / 128), 256>>>(x, wk, k, S_LEN, KV_DIM, DIM);
    sgemm_kernel<<<dim3(KV_DIM / 128, S_LEN / 128), 256>>>(x, wv, v, S_LEN, KV_DIM, DIM);

    // RoPE on Q and K
    rope_kernel<<<(S_LEN * N_HEADS * 64) / 256, 256>>>(q, fc, fs, N_HEADS);
    rope_kernel<<<(S_LEN * N_KV_HEADS * 64) / 256, 256>>>(k, fc, fs, N_KV_HEADS);

    // Attention
    int smem = (BR * DPAD + 2 * BC * DPAD + BR * PCPAD) * (int)sizeof(float);
    cudaFuncSetAttribute(attn_kernel, cudaFuncAttributeMaxDynamicSharedMemorySize, smem);
    attn_kernel<<<dim3(S_LEN / BR, N_HEADS), 256, smem>>>(q, k, v, ao);

    // Output projection
    sgemm_kernel<<<dim3(DIM / 128, S_LEN / 128), 256>>>(ao, wo, out, S_LEN, DIM, DIM);
}